// round 14
// baseline (speedup 1.0000x reference)
#include <cuda_runtime.h>
#include <cuda_bf16.h>
#include <cstdint>

// ---------------------------------------------------------------- constants
#define NB 8
#define SEQ 1024
#define DIN 1280
#define RK 64
#define DOUT 1280
#define DOWN_SZ (RK * DIN)        // 81920
#define UP_SZ (DOUT * RK)         // 81920
#define EMB_STRIDE (DOWN_SZ + UP_SZ)
#define H_ELEMS (NB * SEQ * RK)   // 524288
#define KSPLIT 2
#define KHALF (DIN / KSPLIT)      // 640
#define NCH (KHALF / 64)          // 10 chunks per split

// ------------------------------------------------------------ device scratch
__device__ float         g_hpart[KSPLIT * H_ELEMS]; // split-K fp32 partials (4 MB)
__device__ __align__(16) __nv_bfloat16 g_h_hi[H_ELEMS];
__device__ __align__(16) __nv_bfloat16 g_h_lo[H_ELEMS];
__device__ __align__(16) __nv_bfloat16 g_w_hi[NB * EMB_STRIDE];
__device__ __align__(16) __nv_bfloat16 g_w_lo[NB * EMB_STRIDE];

// ---------------------------------------------------------------- helpers
__device__ __forceinline__ uint32_t s2u(const void* p) {
    uint32_t a;
    asm("{ .reg .u64 t; cvta.to.shared.u64 t, %1; cvt.u32.u64 %0, t; }" : "=r"(a) : "l"(p));
    return a;
}
__device__ __forceinline__ void split2(float x, uint16_t& h, uint16_t& l) {
    __nv_bfloat16 hb = __float2bfloat16(x);
    __nv_bfloat16 lb = __float2bfloat16(x - __bfloat162float(hb));
    h = *(uint16_t*)&hb; l = *(uint16_t*)&lb;
}
__device__ __forceinline__ uint32_t pk(uint16_t a, uint16_t b) {
    return (uint32_t)a | ((uint32_t)b << 16);
}
__device__ __forceinline__ void split8(float4 v0, float4 v1, uint4& hh, uint4& ll) {
    uint16_t h[8], l[8];
    split2(v0.x, h[0], l[0]); split2(v0.y, h[1], l[1]);
    split2(v0.z, h[2], l[2]); split2(v0.w, h[3], l[3]);
    split2(v1.x, h[4], l[4]); split2(v1.y, h[5], l[5]);
    split2(v1.z, h[6], l[6]); split2(v1.w, h[7], l[7]);
    hh = make_uint4(pk(h[0],h[1]), pk(h[2],h[3]), pk(h[4],h[5]), pk(h[6],h[7]));
    ll = make_uint4(pk(l[0],l[1]), pk(l[2],l[3]), pk(l[4],l[5]), pk(l[6],l[7]));
}
__device__ __forceinline__ void ldsm4(uint32_t r[4], uint32_t addr) {
    asm volatile("ldmatrix.sync.aligned.m8n8.x4.shared.b16 {%0,%1,%2,%3}, [%4];"
        : "=r"(r[0]), "=r"(r[1]), "=r"(r[2]), "=r"(r[3]) : "r"(addr));
}
__device__ __forceinline__ void mma_bf16(float d[4], const uint32_t a[4],
                                         uint32_t b0, uint32_t b1) {
    asm volatile(
        "mma.sync.aligned.m16n8k16.row.col.f32.bf16.bf16.f32 "
        "{%0,%1,%2,%3}, {%4,%5,%6,%7}, {%8,%9}, {%0,%1,%2,%3};"
        : "+f"(d[0]), "+f"(d[1]), "+f"(d[2]), "+f"(d[3])
        : "r"(a[0]), "r"(a[1]), "r"(a[2]), "r"(a[3]), "r"(b0), "r"(b1));
}
__device__ __forceinline__ void cpa16(uint32_t saddr, const void* g) {
    asm volatile("cp.async.cg.shared.global [%0], [%1], 16;" :: "r"(saddr), "l"(g));
}
#define CP_COMMIT() asm volatile("cp.async.commit_group;" ::: "memory")
#define CP_WAIT0()  asm volatile("cp.async.wait_group 0;" ::: "memory")

// ---------------------------------------------------------------------------
// prep: split embed (fp32) into bf16 hi/lo. 4 independent chunks/thread.
// ---------------------------------------------------------------------------
#define PREP_T (320 * 256)
__global__ __launch_bounds__(256) void prep_kernel(const float* __restrict__ embed)
{
    const size_t t = (size_t)blockIdx.x * 256 + threadIdx.x;
#pragma unroll
    for (int q = 0; q < 4; q++) {
        const size_t i = (t + (size_t)q * PREP_T) * 4;
        float4 v = *(const float4*)(embed + i);
        uint16_t h0, l0, h1, l1, h2, l2, h3, l3;
        split2(v.x, h0, l0); split2(v.y, h1, l1);
        split2(v.z, h2, l2); split2(v.w, h3, l3);
        *(uint2*)(g_w_hi + i) = make_uint2(pk(h0, h1), pk(h2, h3));
        *(uint2*)(g_w_lo + i) = make_uint2(pk(l0, l1), pk(l2, l3));
    }
}

// ---------------------------------------------------------------------------
// down: h_part[ks] = x[:,ksK:+K] @ Wdown[:,ksK:+K]^T, bf16x3 mma.sync.
// CTA 64x64, split-K=2, 10 K-chunks of 64; DOUBLE-BUFFERED smem pipeline:
// W via cp.async, x via register prefetch + split, overlapped with MMAs.
// ---------------------------------------------------------------------------
#define DST 72                    // smem row stride (conflict-free)
#define ARRE (64 * DST)           // elems per operand array
#define DOWN_SMEM (2 * 4 * ARRE * 2)   // 73728 bytes
__global__ __launch_bounds__(256) void down_kernel(const float* __restrict__ x)
{
    extern __shared__ __align__(16) uint16_t dsm[];

    const int tid = threadIdx.x, lane = tid & 31, wid = tid >> 5;
    const int ks = blockIdx.x, mt = blockIdx.y, b = blockIdx.z;
    const int kbeg = ks * KHALF;

    const float* A = x + ((size_t)b * SEQ + (size_t)mt * 64) * DIN;
    const __nv_bfloat16* WH = g_w_hi + (size_t)b * EMB_STRIDE;
    const __nv_bfloat16* WL = g_w_lo + (size_t)b * EMB_STRIDE;
    float* C = g_hpart + (size_t)ks * H_ELEMS + ((size_t)b * SEQ + (size_t)mt * 64) * RK;

    const int lrow = tid >> 2, lcs = (tid & 3) * 16;     // loader mapping
    const int wm = (wid & 1) * 32, wn = (wid >> 1) * 16; // warp tiling 2(M) x 4(N)

    const uint32_t sbase = s2u(dsm);
    const uint32_t ldoff = (uint32_t)(lrow * DST + lcs) * 2;  // loader byte offset
    const int aoff = (lane & 15) * DST + (lane >> 4) * 8;
    const int boff = (((lane >> 3) & 1) * 8 + (lane & 7)) * DST + (lane >> 4) * 8;

    float acc[2][2][4];
#pragma unroll
    for (int i = 0; i < 2; i++)
#pragma unroll
        for (int j = 0; j < 2; j++)
#pragma unroll
            for (int q = 0; q < 4; q++) acc[i][j][q] = 0.f;

    // ---- prologue: chunk 0 into buffer 0
    {
        const float* ap = A + (size_t)lrow * DIN + kbeg + lcs;
        float4 xv0 = *(const float4*)ap,       xv1 = *(const float4*)(ap + 4);
        float4 xv2 = *(const float4*)(ap + 8), xv3 = *(const float4*)(ap + 12);
        const __nv_bfloat16* wh = WH + (size_t)lrow * DIN + kbeg + lcs;
        const __nv_bfloat16* wl = WL + (size_t)lrow * DIN + kbeg + lcs;
        cpa16(sbase + 2 * ARRE * 2 + ldoff,      wh);
        cpa16(sbase + 2 * ARRE * 2 + ldoff + 16, wh + 8);
        cpa16(sbase + 3 * ARRE * 2 + ldoff,      wl);
        cpa16(sbase + 3 * ARRE * 2 + ldoff + 16, wl + 8);
        CP_COMMIT();
        uint4 hh0, ll0, hh1, ll1;
        split8(xv0, xv1, hh0, ll0);
        split8(xv2, xv3, hh1, ll1);
        uint16_t* p = dsm + lrow * DST + lcs;
        *(uint4*)p = hh0; *(uint4*)(p + 8) = hh1;
        p += ARRE;
        *(uint4*)p = ll0; *(uint4*)(p + 8) = ll1;
        CP_WAIT0();
    }
    __syncthreads();

    for (int ch = 0; ch < NCH; ch++) {
        const int cur = ch & 1;
        const uint32_t curB = (uint32_t)(cur * 4 * ARRE * 2);
        const uint32_t nxtB = (uint32_t)((cur ^ 1) * 4 * ARRE * 2);

        // prefetch next chunk: x into regs, W via cp.async into other buffer
        float4 xv0, xv1, xv2, xv3;
        if (ch + 1 < NCH) {
            const int kc = kbeg + (ch + 1) * 64;
            const float* ap = A + (size_t)lrow * DIN + kc + lcs;
            xv0 = *(const float4*)ap;       xv1 = *(const float4*)(ap + 4);
            xv2 = *(const float4*)(ap + 8); xv3 = *(const float4*)(ap + 12);
            const __nv_bfloat16* wh = WH + (size_t)lrow * DIN + kc + lcs;
            const __nv_bfloat16* wl = WL + (size_t)lrow * DIN + kc + lcs;
            cpa16(sbase + nxtB + 2 * ARRE * 2 + ldoff,      wh);
            cpa16(sbase + nxtB + 2 * ARRE * 2 + ldoff + 16, wh + 8);
            cpa16(sbase + nxtB + 3 * ARRE * 2 + ldoff,      wl);
            cpa16(sbase + nxtB + 3 * ARRE * 2 + ldoff + 16, wl + 8);
            CP_COMMIT();
        }

        // compute from current buffer
        const uint32_t ahb = sbase + curB;
        const uint32_t alb = ahb + ARRE * 2;
        const uint32_t bhb = ahb + 2 * ARRE * 2;
        const uint32_t blb = ahb + 3 * ARRE * 2;
#pragma unroll
        for (int ks2 = 0; ks2 < 4; ks2++) {
            const int kb = ks2 * 16;
            uint32_t ah0[4], ah1[4], al0[4], al1[4], bh[4], bl[4];
            ldsm4(ah0, ahb + (uint32_t)(wm * DST + kb + aoff) * 2);
            ldsm4(ah1, ahb + (uint32_t)((wm + 16) * DST + kb + aoff) * 2);
            ldsm4(al0, alb + (uint32_t)(wm * DST + kb + aoff) * 2);
            ldsm4(al1, alb + (uint32_t)((wm + 16) * DST + kb + aoff) * 2);
            ldsm4(bh,  bhb + (uint32_t)(wn * DST + kb + boff) * 2);
            ldsm4(bl,  blb + (uint32_t)(wn * DST + kb + boff) * 2);
            mma_bf16(acc[0][0], ah0, bh[0], bh[2]);
            mma_bf16(acc[0][0], ah0, bl[0], bl[2]);
            mma_bf16(acc[0][0], al0, bh[0], bh[2]);
            mma_bf16(acc[0][1], ah0, bh[1], bh[3]);
            mma_bf16(acc[0][1], ah0, bl[1], bl[3]);
            mma_bf16(acc[0][1], al0, bh[1], bh[3]);
            mma_bf16(acc[1][0], ah1, bh[0], bh[2]);
            mma_bf16(acc[1][0], ah1, bl[0], bl[2]);
            mma_bf16(acc[1][0], al1, bh[0], bh[2]);
            mma_bf16(acc[1][1], ah1, bh[1], bh[3]);
            mma_bf16(acc[1][1], ah1, bl[1], bl[3]);
            mma_bf16(acc[1][1], al1, bh[1], bh[3]);
        }

        // finish staging next buffer
        if (ch + 1 < NCH) {
            uint4 hh0, ll0, hh1, ll1;
            split8(xv0, xv1, hh0, ll0);
            split8(xv2, xv3, hh1, ll1);
            uint16_t* p = dsm + (cur ^ 1) * 4 * ARRE + lrow * DST + lcs;
            *(uint4*)p = hh0; *(uint4*)(p + 8) = hh1;
            p += ARRE;
            *(uint4*)p = ll0; *(uint4*)(p + 8) = ll1;
            CP_WAIT0();
        }
        __syncthreads();
    }

    // epilogue: write fp32 partial h
    const int er = lane >> 2, ec = (lane & 3) * 2;
#pragma unroll
    for (int mf = 0; mf < 2; mf++)
#pragma unroll
        for (int nf = 0; nf < 2; nf++) {
            float* c0 = C + (size_t)(wm + mf * 16 + er) * RK + wn + nf * 8 + ec;
            *(float2*)c0            = make_float2(acc[mf][nf][0], acc[mf][nf][1]);
            *(float2*)(c0 + 8 * RK) = make_float2(acc[mf][nf][2], acc[mf][nf][3]);
        }
}

// ---------------------------------------------------------------------------
// reduce: h = part0 + part1, emitted once as bf16 hi/lo.
// ---------------------------------------------------------------------------
__global__ __launch_bounds__(256) void reduce_kernel()
{
    const size_t i = ((size_t)blockIdx.x * 256 + threadIdx.x) * 4;
    float4 a = *(const float4*)(g_hpart + i);
    float4 c = *(const float4*)(g_hpart + (size_t)H_ELEMS + i);
    a.x += c.x; a.y += c.y; a.z += c.z; a.w += c.w;
    uint16_t h0, l0, h1, l1, h2, l2, h3, l3;
    split2(a.x, h0, l0); split2(a.y, h1, l1);
    split2(a.z, h2, l2); split2(a.w, h3, l3);
    *(uint2*)(g_h_hi + i) = make_uint2(pk(h0, h1), pk(h2, h3));
    *(uint2*)(g_h_lo + i) = make_uint2(pk(l0, l1), pk(l2, l3));
}

// ---------------------------------------------------------------------------
// up: out = h @ Wup^T, bf16x3 mma.sync. CTA does TWO 128-row M-tiles with the
// 128x64 B tile RESIDENT in smem; A double-buffered via cp.async so A(mt1)
// streams in during compute+store of mt0.  grid = 10 x 4 x 8 = 320 CTAs.
// ---------------------------------------------------------------------------
#define NDE (128 * DST)           // elems per operand array
#define UP_SMEM (6 * NDE * 2)     // BH,BL + 2x(AH,AL) = 110592 bytes
__global__ __launch_bounds__(256) void up_kernel(float* __restrict__ out)
{
    extern __shared__ __align__(16) uint16_t usm[];
    // layout (elems): BH=0, BL=NDE, A0H=2*NDE, A0L=3*NDE, A1H=4*NDE, A1L=5*NDE

    const int tid = threadIdx.x, lane = tid & 31, wid = tid >> 5;
    const int nt = blockIdx.x, mg = blockIdx.y, b = blockIdx.z;

    const __nv_bfloat16* WH = g_w_hi + (size_t)b * EMB_STRIDE + DOWN_SZ + (size_t)nt * 128 * RK;
    const __nv_bfloat16* WL = g_w_lo + (size_t)b * EMB_STRIDE + DOWN_SZ + (size_t)nt * 128 * RK;

    const uint32_t sbase = s2u(usm);
    const int lrow = tid >> 1, lcs = (tid & 1) * 32;     // loader: row, 32-col seg
    const uint32_t ldoff = (uint32_t)(lrow * DST + lcs) * 2;

    // ---- prologue: B + A(mt0) via cp.async
    {
        const __nv_bfloat16* ah = g_h_hi + ((size_t)b * SEQ + (size_t)(mg * 2) * 128 + lrow) * RK + lcs;
        const __nv_bfloat16* al = g_h_lo + ((size_t)b * SEQ + (size_t)(mg * 2) * 128 + lrow) * RK + lcs;
        const __nv_bfloat16* wh = WH + (size_t)lrow * RK + lcs;
        const __nv_bfloat16* wl = WL + (size_t)lrow * RK + lcs;
#pragma unroll
        for (int j = 0; j < 4; j++) {
            cpa16(sbase + ldoff + j * 16,                wh + j * 8);
            cpa16(sbase + NDE * 2 + ldoff + j * 16,      wl + j * 8);
            cpa16(sbase + 2 * NDE * 2 + ldoff + j * 16,  ah + j * 8);
            cpa16(sbase + 3 * NDE * 2 + ldoff + j * 16,  al + j * 8);
        }
        CP_COMMIT();
        CP_WAIT0();
    }
    __syncthreads();

    const int wm = (wid & 3) * 32, wn = (wid >> 2) * 64;  // warp tile 32x64
    const uint32_t bhb = sbase, blb = sbase + NDE * 2;
    const int aoff = (lane & 15) * DST + (lane >> 4) * 8;
    const int boff = (((lane >> 3) & 1) * 8 + (lane & 7)) * DST + (lane >> 4) * 8;

#pragma unroll
    for (int i = 0; i < 2; i++) {
        // prefetch A(mt1) while computing mt0
        if (i == 0) {
            const __nv_bfloat16* ah = g_h_hi + ((size_t)b * SEQ + (size_t)(mg * 2 + 1) * 128 + lrow) * RK + lcs;
            const __nv_bfloat16* al = g_h_lo + ((size_t)b * SEQ + (size_t)(mg * 2 + 1) * 128 + lrow) * RK + lcs;
#pragma unroll
            for (int j = 0; j < 4; j++) {
                cpa16(sbase + 4 * NDE * 2 + ldoff + j * 16, ah + j * 8);
                cpa16(sbase + 5 * NDE * 2 + ldoff + j * 16, al + j * 8);
            }
            CP_COMMIT();
        }

        const uint32_t ahb = sbase + (uint32_t)(2 + 2 * i) * NDE * 2;
        const uint32_t alb = ahb + NDE * 2;

        float acc[2][8][4];
#pragma unroll
        for (int m2 = 0; m2 < 2; m2++)
#pragma unroll
            for (int j = 0; j < 8; j++)
#pragma unroll
                for (int q = 0; q < 4; q++) acc[m2][j][q] = 0.f;

#pragma unroll
        for (int ks = 0; ks < 4; ks++) {
            const int kb = ks * 16;
            uint32_t ah[2][4], al[2][4];
            ldsm4(ah[0], ahb + (uint32_t)(wm * DST + kb + aoff) * 2);
            ldsm4(ah[1], ahb + (uint32_t)((wm + 16) * DST + kb + aoff) * 2);
            ldsm4(al[0], alb + (uint32_t)(wm * DST + kb + aoff) * 2);
            ldsm4(al[1], alb + (uint32_t)((wm + 16) * DST + kb + aoff) * 2);
            uint32_t bh[4][4], bl[4][4];
#pragma unroll
            for (int p = 0; p < 4; p++) {
                ldsm4(bh[p], bhb + (uint32_t)((wn + p * 16) * DST + kb + boff) * 2);
                ldsm4(bl[p], blb + (uint32_t)((wn + p * 16) * DST + kb + boff) * 2);
            }
#pragma unroll
            for (int mf = 0; mf < 2; mf++)
#pragma unroll
                for (int p = 0; p < 4; p++) {
                    mma_bf16(acc[mf][2*p],   ah[mf], bh[p][0], bh[p][2]);
                    mma_bf16(acc[mf][2*p],   ah[mf], bl[p][0], bl[p][2]);
                    mma_bf16(acc[mf][2*p],   al[mf], bh[p][0], bh[p][2]);
                    mma_bf16(acc[mf][2*p+1], ah[mf], bh[p][1], bh[p][3]);
                    mma_bf16(acc[mf][2*p+1], ah[mf], bl[p][1], bl[p][3]);
                    mma_bf16(acc[mf][2*p+1], al[mf], bh[p][1], bh[p][3]);
                }
        }

        // epilogue for this m-tile
        float* O = out + ((size_t)b * SEQ + (size_t)(mg * 2 + i) * 128) * DOUT + (size_t)nt * 128;
        const int er = lane >> 2, ec = (lane & 3) * 2;
#pragma unroll
        for (int mf = 0; mf < 2; mf++)
#pragma unroll
            for (int nf = 0; nf < 8; nf++) {
                float* c0 = O + (size_t)(wm + mf * 16 + er) * DOUT + wn + nf * 8 + ec;
                *(float2*)c0              = make_float2(acc[mf][nf][0], acc[mf][nf][1]);
                *(float2*)(c0 + 8 * DOUT) = make_float2(acc[mf][nf][2], acc[mf][nf][3]);
            }

        if (i == 0) {
            CP_WAIT0();
            __syncthreads();
        }
    }
}

// ---------------------------------------------------------------------------
extern "C" void kernel_launch(void* const* d_in, const int* in_sizes, int n_in,
                              void* d_out, int out_size)
{
    const float* x     = (const float*)d_in[0];   // [B, S, D_IN] fp32
    const float* embed = (const float*)d_in[1];   // [B, DOWN+UP] fp32
    float*       out   = (float*)d_out;           // [B, S, D_OUT] fp32
    (void)in_sizes; (void)n_in; (void)out_size;

    cudaFuncSetAttribute(down_kernel, cudaFuncAttributeMaxDynamicSharedMemorySize, DOWN_SMEM);
    cudaFuncSetAttribute(up_kernel,   cudaFuncAttributeMaxDynamicSharedMemorySize, UP_SMEM);

    // 1) split embed into bf16 hi/lo
    prep_kernel<<<320, 256>>>(embed);
    // 2) down GEMM split-K=2: grid 2 x 16 x 8 = 256 CTAs (one wave at 2/SM)
    down_kernel<<<dim3(KSPLIT, SEQ / 64, NB), 256, DOWN_SMEM>>>(x);
    // 3) reduce partials -> bf16 hi/lo h
    reduce_kernel<<<H_ELEMS / 4 / 256, 256>>>();
    // 4) up GEMM: grid 10 x 4 x 8 = 320 CTAs, 2 m-tiles each
    up_kernel<<<dim3(DOUT / 128, SEQ / 256, NB), 256, UP_SMEM>>>(out);
}